// round 7
// baseline (speedup 1.0000x reference)
#include <cuda_runtime.h>
#include <math_constants.h>

// Pooling_21577915695109: out[b,n,:] = max over m of x_pad[b, index[n,m], :]
// x: (4, 50000, 64) fp32, index: (50000, 16) int32 in [0, 50000]; idx==50000 -> zero row.
//
// R7 shape: shuffle-free index distribution. All 16 lanes of a node-group load
// the node's indices as int4 broadcasts (L1-hit, 1 wavefront) instead of
// lane-exchange via SHFL — removes 16 MIO shuffle ops per thread per batch,
// which R6 ncu showed as the co-limiter (L1=72%, alu=44%).

constexpr int N_NODES = 50000;
constexpr int M_NEIGH = 16;
constexpr int HID     = 64;

constexpr int THREADS_PER_NODE = 16;   // 16 lanes x float4 = 64 floats = one row
constexpr int NODES_PER_BLOCK  = 16;   // 256 threads / block
constexpr int BLOCK_THREADS    = THREADS_PER_NODE * NODES_PER_BLOCK;

__device__ __forceinline__ float4 fmax4(float4 a, float4 b) {
    return make_float4(fmaxf(a.x, b.x), fmaxf(a.y, b.y),
                       fmaxf(a.z, b.z), fmaxf(a.w, b.w));
}

__global__ __launch_bounds__(BLOCK_THREADS)
void pool_max_kernel(const float* __restrict__ x,
                     const int* __restrict__ index,
                     float* __restrict__ out)
{
    const int lane  = threadIdx.x & (THREADS_PER_NODE - 1);
    const int group = threadIdx.x >> 4;
    const int node  = blockIdx.x * NODES_PER_BLOCK + group;   // grid.x*16 == N exactly
    const int batch = blockIdx.y;

    // Row pointer pre-biased by this lane's column quad: gather = base + idx*64.
    const float* __restrict__ xb = x + (size_t)batch * (N_NODES * HID) + lane * 4;

    // This node's 16 neighbor indices, loaded as 4 x int4 broadcasts
    // (all 16 lanes of the group hit the same address -> single wavefront, L1-hit).
    const int4* __restrict__ idx4 = (const int4*)(index + node * M_NEIGH);

    float4 acc = make_float4(-CUDART_INF_F, -CUDART_INF_F, -CUDART_INF_F, -CUDART_INF_F);
    const float4 zero4 = make_float4(0.f, 0.f, 0.f, 0.f);

    #pragma unroll
    for (int c = 0; c < 4; c++) {
        const int4 iv = __ldg(idx4 + c);
        const int ids[4] = { iv.x, iv.y, iv.z, iv.w };

        #pragma unroll
        for (int j = 0; j < 4; j++) {
            const int idx = ids[j];
            // Unsigned compare: the N_NODES sentinel (and anything unexpected)
            // takes the zero-row path -> no OOB possible.
            const bool valid = ((unsigned)idx < (unsigned)N_NODES);
            const float4 v = valid ? __ldg((const float4*)(xb + (unsigned)idx * HID))
                                   : zero4;
            acc = fmax4(acc, v);
        }
    }

    const size_t obase = (size_t)batch * (N_NODES * HID)
                       + (unsigned)node * HID + (unsigned)lane * 4;
    *(float4*)(out + obase) = acc;
}

extern "C" void kernel_launch(void* const* d_in, const int* in_sizes, int n_in,
                              void* d_out, int out_size)
{
    const float* x     = (const float*)d_in[0];  // (4, 50000, 64) fp32
    const int*   index = (const int*)d_in[1];    // (50000, 16) int32
    float*       out   = (float*)d_out;          // (4, 50000, 64) fp32

    dim3 grid(N_NODES / NODES_PER_BLOCK, 4);     // 3125 x 4, exact cover
    pool_max_kernel<<<grid, BLOCK_THREADS>>>(x, index, out);
}